// round 1
// baseline (speedup 1.0000x reference)
#include <cuda_runtime.h>
#include <math.h>

#define NB 128
#define NI 1152
#define NN 16
#define NE 16
#define ND 8
#define HAT_PER_B (NI*NN*NE)    // 294912 floats per batch
#define S_SIZE (NB*NN*NE)       // 32768
#define ICHUNKS 9               // 1152 / 128

// Scratch (static device globals; no runtime allocation)
__device__ float g_hat[(size_t)NB * HAT_PER_B];      // [b][i][n*16+e], 151 MB
__device__ float g_s0p[ICHUNKS * S_SIZE];            // partial sums over i-chunks
__device__ float g_out0[S_SIZE];                     // squash(s0)

// ---------------------------------------------------------------------------
// k_hat: hat[b,i,n,e] = sum_d x[b,i,d] * W[n,i,e,d]
// grid (9 i-chunks of 128, 16 b-blocks of 8), 256 threads: t = n*16+e.
// Also accumulates per-chunk partial of sum_i hat (for iter-0 s).
// ---------------------------------------------------------------------------
__global__ void __launch_bounds__(256) k_hat(const float* __restrict__ x,
                                             const float* __restrict__ W) {
    __shared__ float4 sx[8][128][2];   // x[b0..b0+8][i0..i0+128][0..8], 32KB
    const int t  = threadIdx.x;
    const int i0 = blockIdx.x * 128;
    const int b0 = blockIdx.y * 8;

    // Stage x tile (coalesced float4 loads)
    const float4* xg = reinterpret_cast<const float4*>(x);
    for (int idx = t; idx < 8 * 256; idx += 256) {
        int bb  = idx >> 8;          // 0..7
        int rem = idx & 255;         // i*2 + j
        sx[bb][rem >> 1][rem & 1] = xg[((size_t)(b0 + bb) * NI + i0) * 2 + rem];
    }
    __syncthreads();

    const int n = t >> 4, e = t & 15;
    const float4* wp = reinterpret_cast<const float4*>(W)
                     + ((size_t)(n * NI + i0) * NE + e) * 2;

    float s0acc[8];
#pragma unroll
    for (int bb = 0; bb < 8; ++bb) s0acc[bb] = 0.f;

    for (int i = 0; i < 128; ++i) {
        float4 w0 = wp[0], w1 = wp[1];
        wp += NE * 2;   // advance one i (NE*ND floats)
        size_t obase = ((size_t)(b0) * NI + (i0 + i)) * 256 + t;
#pragma unroll
        for (int bb = 0; bb < 8; ++bb) {
            float4 x0 = sx[bb][i][0], x1 = sx[bb][i][1];
            float h = w0.x*x0.x + w0.y*x0.y + w0.z*x0.z + w0.w*x0.w
                    + w1.x*x1.x + w1.y*x1.y + w1.z*x1.z + w1.w*x1.w;
            g_hat[obase + (size_t)bb * (NI * 256)] = h;
            s0acc[bb] += h;
        }
    }
#pragma unroll
    for (int bb = 0; bb < 8; ++bb)
        g_s0p[blockIdx.x * S_SIZE + (b0 + bb) * 256 + t] = s0acc[bb];
}

// squash along e using warp butterfly over low 4 lane bits (t = n*16+e)
__device__ __forceinline__ float squash_val(float sv) {
    float sq = sv * sv;
    sq += __shfl_xor_sync(0xffffffffu, sq, 1);
    sq += __shfl_xor_sync(0xffffffffu, sq, 2);
    sq += __shfl_xor_sync(0xffffffffu, sq, 4);
    sq += __shfl_xor_sync(0xffffffffu, sq, 8);
    float scale = sq / ((1.f + sq) * sqrtf(sq));
    return sv * scale;
}

// ---------------------------------------------------------------------------
// k_squash0: s0 = (1/16)*sum_i hat + Bias ; out0 = squash(s0)
// grid 128 (b), 256 threads (t = n*16+e)
// ---------------------------------------------------------------------------
__global__ void __launch_bounds__(256) k_squash0(const float* __restrict__ Bias) {
    const int b = blockIdx.x, t = threadIdx.x;
    float sv = 0.f;
#pragma unroll
    for (int c = 0; c < ICHUNKS; ++c) sv += g_s0p[c * S_SIZE + b * 256 + t];
    sv = sv * (1.f / 16.f) + Bias[t];
    g_out0[b * 256 + t] = squash_val(sv);
}

// ---------------------------------------------------------------------------
// One streaming routing pass over hat for batch b:
//   logits[i][n] = dot(vec[n][:], hat[i][n][:])  (vec = cumulative outputs)
//   c = softmax over n ; sacc[n][e] += c * hat
// Lane l owns (n = l>>1, e-range = (l&1)*8 .. +8). Warp w handles i = w,
// w+16, ... 1-deep register prefetch for memory-level parallelism.
// ---------------------------------------------------------------------------
__device__ __forceinline__ void route_pass(const float4* __restrict__ p0,
                                           int warp, const float vec[8],
                                           float sacc[8]) {
#pragma unroll
    for (int k = 0; k < 8; ++k) sacc[k] = 0.f;
    const int STEP = 16 * 64;            // 16 i's * 64 float4/i
    const float4* p = p0;
    float4 a0 = p[0], a1 = p[1];
    for (int i = warp; i < NI; i += 16) {
        float4 b0, b1;
        if (i + 16 < NI) { b0 = p[STEP]; b1 = p[STEP + 1]; }
        p += STEP;

        float pl = vec[0]*a0.x + vec[1]*a0.y + vec[2]*a0.z + vec[3]*a0.w
                 + vec[4]*a1.x + vec[5]*a1.y + vec[6]*a1.z + vec[7]*a1.w;
        pl += __shfl_xor_sync(0xffffffffu, pl, 1);     // full dot over 16 e
        float E = __expf(pl);
        float d = E;
        d += __shfl_xor_sync(0xffffffffu, d, 2);
        d += __shfl_xor_sync(0xffffffffu, d, 4);
        d += __shfl_xor_sync(0xffffffffu, d, 8);
        d += __shfl_xor_sync(0xffffffffu, d, 16);      // softmax denom over n
        float c = E / d;

        sacc[0] += c*a0.x; sacc[1] += c*a0.y; sacc[2] += c*a0.z; sacc[3] += c*a0.w;
        sacc[4] += c*a1.x; sacc[5] += c*a1.y; sacc[6] += c*a1.z; sacc[7] += c*a1.w;
        a0 = b0; a1 = b1;
    }
}

// ---------------------------------------------------------------------------
// k_route: passes for routing iterations 1 and 2 (iter 0 handled by k_squash0).
// b2 = (out0 + out1)·hat telescoping means no logit storage is needed.
// grid 128 (b), 512 threads (16 warps).
// ---------------------------------------------------------------------------
__global__ void __launch_bounds__(512) k_route(const float* __restrict__ Bias,
                                               float* __restrict__ out) {
    __shared__ float sp[16][256];       // per-warp partial s
    __shared__ float sOut[256];
    __shared__ float sBias[256];

    const int b = blockIdx.x, t = threadIdx.x;
    const int warp = t >> 5, lane = t & 31;
    if (t < 256) sBias[t] = Bias[t];
    __syncthreads();

    const float4* hb4 = reinterpret_cast<const float4*>(g_hat)
                      + (size_t)b * (HAT_PER_B / 4);
    const float4* plane = hb4 + warp * 64 + lane * 2;  // lane*8 floats offset

    // vec0 = out0 (iteration-0 output)
    float vec0[8], vec[8], sacc[8];
    {
        const float4* o4 = reinterpret_cast<const float4*>(g_out0) + b * 64 + lane * 2;
        float4 v0 = o4[0], v1 = o4[1];
        vec0[0]=v0.x; vec0[1]=v0.y; vec0[2]=v0.z; vec0[3]=v0.w;
        vec0[4]=v1.x; vec0[5]=v1.y; vec0[6]=v1.z; vec0[7]=v1.w;
    }

    // ---- Pass 1: b1 = out0·hat, c1 = softmax, s1, out1 ----
    route_pass(plane, warp, vec0, sacc);
#pragma unroll
    for (int k = 0; k < 8; ++k) sp[warp][lane * 8 + k] = sacc[k];
    __syncthreads();
    if (t < 256) {
        float sv = sBias[t];
#pragma unroll
        for (int w = 0; w < 16; ++w) sv += sp[w][t];
        sOut[t] = squash_val(sv);
    }
    __syncthreads();
#pragma unroll
    for (int k = 0; k < 8; ++k) vec[k] = vec0[k] + sOut[lane * 8 + k];
    __syncthreads();

    // ---- Pass 2: b2 = (out0+out1)·hat, c2 = softmax, s2, final squash ----
    route_pass(plane, warp, vec, sacc);
#pragma unroll
    for (int k = 0; k < 8; ++k) sp[warp][lane * 8 + k] = sacc[k];
    __syncthreads();
    if (t < 256) {
        float sv = sBias[t];
#pragma unroll
        for (int w = 0; w < 16; ++w) sv += sp[w][t];
        out[b * 256 + t] = squash_val(sv);
    }
}

extern "C" void kernel_launch(void* const* d_in, const int* in_sizes, int n_in,
                              void* d_out, int out_size) {
    const float* x    = (const float*)d_in[0];   // [128,1152,8]
    const float* W    = (const float*)d_in[1];   // [16,1152,16,8]
    const float* Bias = (const float*)d_in[2];   // [16,16]
    float* out = (float*)d_out;                  // [128,16,16]

    dim3 g1(ICHUNKS, 16);
    k_hat<<<g1, 256>>>(x, W);
    k_squash0<<<128, 256>>>(Bias);
    k_route<<<128, 512>>>(Bias, out);
}

// round 2
// speedup vs baseline: 1.9844x; 1.9844x over previous
#include <cuda_runtime.h>
#include <cuda_fp16.h>
#include <math.h>

#define NB 128
#define NI 1152
#define NN 16
#define NE 16
#define HAT_PER_B (NI*NN*NE)    // 294912 per batch
#define S_SIZE (NB*NN*NE)       // 32768
#define IC 32                   // i per k_hat CTA
#define BC 8                    // b per k_hat CTA
#define ICHUNKS (NI/IC)         // 36
#define RWARPS 32               // warps in k_route

// Scratch (static device globals; no runtime allocation)
__device__ __half g_hat[(size_t)NB * HAT_PER_B];   // [b][i][n*16+e], 75.5 MB (L2-resident)
__device__ float  g_s0p[ICHUNKS * S_SIZE];         // per-i-chunk partials of sum_i hat

// ---------------------------------------------------------------------------
// k_hat: hat[b,i,n,e] = sum_d x[b,i,d] * W[n,i,e,d], stored fp16.
// grid (36 i-chunks of 32, 16 b-blocks of 8), 256 threads: t = n*16+e.
// Also accumulates per-chunk partial of sum_i hat (iter-0 s, uniform softmax).
// ---------------------------------------------------------------------------
__global__ void __launch_bounds__(256) k_hat(const float* __restrict__ x,
                                             const float* __restrict__ W) {
    __shared__ float4 sx[BC][IC][2];   // 8KB x tile
    const int t  = threadIdx.x;
    const int i0 = blockIdx.x * IC;
    const int b0 = blockIdx.y * BC;

    // Stage x tile (coalesced float4 loads): BC*IC*2 = 512 float4, 2 per thread
    const float4* xg = reinterpret_cast<const float4*>(x);
    for (int idx = t; idx < BC * IC * 2; idx += 256) {
        int bb  = idx >> 6;          // /64
        int rem = idx & 63;          // i*2 + j
        sx[bb][rem >> 1][rem & 1] = xg[((size_t)(b0 + bb) * NI + i0) * 2 + rem];
    }
    __syncthreads();

    const int n = t >> 4, e = t & 15;
    const float4* wp = reinterpret_cast<const float4*>(W)
                     + ((size_t)(n * NI + i0) * NE + e) * 2;

    float s0acc[BC];
#pragma unroll
    for (int bb = 0; bb < BC; ++bb) s0acc[bb] = 0.f;

    float4 w0 = wp[0], w1 = wp[1];
    for (int i = 0; i < IC; ++i) {
        float4 nw0, nw1;
        if (i + 1 < IC) { nw0 = wp[NE * 2]; nw1 = wp[NE * 2 + 1]; }
        wp += NE * 2;
        size_t obase = ((size_t)b0 * NI + (i0 + i)) * 256 + t;
#pragma unroll
        for (int bb = 0; bb < BC; ++bb) {
            float4 x0 = sx[bb][i][0], x1 = sx[bb][i][1];
            float h = w0.x*x0.x + w0.y*x0.y + w0.z*x0.z + w0.w*x0.w
                    + w1.x*x1.x + w1.y*x1.y + w1.z*x1.z + w1.w*x1.w;
            g_hat[obase + (size_t)bb * (NI * 256)] = __float2half_rn(h);
            s0acc[bb] += h;
        }
        w0 = nw0; w1 = nw1;
    }
#pragma unroll
    for (int bb = 0; bb < BC; ++bb)
        g_s0p[blockIdx.x * S_SIZE + (b0 + bb) * 256 + t] = s0acc[bb];
}

// squash along e using warp butterfly over low 4 lane bits (t = n*16+e)
__device__ __forceinline__ float squash_val(float sv) {
    float sq = sv * sv;
    sq += __shfl_xor_sync(0xffffffffu, sq, 1);
    sq += __shfl_xor_sync(0xffffffffu, sq, 2);
    sq += __shfl_xor_sync(0xffffffffu, sq, 4);
    sq += __shfl_xor_sync(0xffffffffu, sq, 8);
    float scale = sq / ((1.f + sq) * sqrtf(sq));
    return sv * scale;
}

// ---------------------------------------------------------------------------
// One streaming routing pass over fp16 hat for batch b:
//   logit[i][n] = dot(vec[n][:], hat[i][n][:]) ; c = softmax over n
//   sacc[n][e] += c * hat
// Lane l owns (n = l>>1, e-range (l&1)*8..+8). Warp w handles i = w, w+32,...
// 2-deep register prefetch (uint4 = 8 halves = 16B per lane per i).
// ---------------------------------------------------------------------------
__device__ __forceinline__ void route_pass(const uint4* __restrict__ p0,
                                           const float vec[8], float sacc[8]) {
#pragma unroll
    for (int k = 0; k < 8; ++k) sacc[k] = 0.f;
    const int STEP = RWARPS * 32;          // 32 warps * 32 uint4 per i
    const int NIT  = NI / RWARPS;          // 36
    const uint4* p = p0;
    uint4 A = p[0], B = p[STEP];
    for (int it = 0; it < NIT; ++it) {
        uint4 C;
        if (it + 2 < NIT) C = p[2 * STEP];
        p += STEP;

        const __half2* hp = reinterpret_cast<const __half2*>(&A);
        float2 f0 = __half22float2(hp[0]);
        float2 f1 = __half22float2(hp[1]);
        float2 f2 = __half22float2(hp[2]);
        float2 f3 = __half22float2(hp[3]);

        float pl = vec[0]*f0.x + vec[1]*f0.y + vec[2]*f1.x + vec[3]*f1.y
                 + vec[4]*f2.x + vec[5]*f2.y + vec[6]*f3.x + vec[7]*f3.y;
        pl += __shfl_xor_sync(0xffffffffu, pl, 1);     // full dot over 16 e
        float E = __expf(pl);
        float d = E;
        d += __shfl_xor_sync(0xffffffffu, d, 2);
        d += __shfl_xor_sync(0xffffffffu, d, 4);
        d += __shfl_xor_sync(0xffffffffu, d, 8);
        d += __shfl_xor_sync(0xffffffffu, d, 16);      // softmax denom over n
        float c = E * __frcp_rn(d);

        sacc[0] += c*f0.x; sacc[1] += c*f0.y; sacc[2] += c*f1.x; sacc[3] += c*f1.y;
        sacc[4] += c*f2.x; sacc[5] += c*f2.y; sacc[6] += c*f3.x; sacc[7] += c*f3.y;
        A = B; B = C;
    }
}

// ---------------------------------------------------------------------------
// k_route: iter-0 squash (from g_s0p partials) + routing passes 1 and 2.
// Telescoped logits: b1 = out0·hat, b2 = (out0+out1)·hat — no logit storage.
// grid 128 (b), 1024 threads (32 warps).
// ---------------------------------------------------------------------------
__global__ void __launch_bounds__(1024) k_route(const float* __restrict__ Bias,
                                                float* __restrict__ out) {
    __shared__ float sp[RWARPS][256];   // per-warp partial s (32KB)
    __shared__ float sOut[256];
    __shared__ float sBias[256];

    const int b = blockIdx.x, t = threadIdx.x;
    const int warp = t >> 5, lane = t & 31;
    if (t < 256) sBias[t] = Bias[t];
    __syncthreads();

    // ---- Iter 0: uniform softmax -> s0 = (1/16)*sum_i hat + Bias ----
    if (t < 256) {
        float sv = 0.f;
#pragma unroll
        for (int c = 0; c < ICHUNKS; ++c) sv += g_s0p[c * S_SIZE + b * 256 + t];
        sv = sv * (1.f / 16.f) + sBias[t];
        sOut[t] = squash_val(sv);
    }
    __syncthreads();

    const uint4* plane = reinterpret_cast<const uint4*>(g_hat)
                       + (size_t)b * (NI * 32) + warp * 32 + lane;

    float vec0[8], vec[8], sacc[8];
#pragma unroll
    for (int k = 0; k < 8; ++k) vec0[k] = sOut[lane * 8 + k];
    __syncthreads();

    // ---- Pass 1: b1 = out0 . hat ----
    route_pass(plane, vec0, sacc);
#pragma unroll
    for (int k = 0; k < 8; ++k) sp[warp][lane * 8 + k] = sacc[k];
    __syncthreads();
    if (t < 256) {
        float sv = sBias[t];
#pragma unroll
        for (int w = 0; w < RWARPS; ++w) sv += sp[w][t];
        sOut[t] = squash_val(sv);
    }
    __syncthreads();
#pragma unroll
    for (int k = 0; k < 8; ++k) vec[k] = vec0[k] + sOut[lane * 8 + k];
    __syncthreads();

    // ---- Pass 2: b2 = (out0+out1) . hat, final squash ----
    route_pass(plane, vec, sacc);
#pragma unroll
    for (int k = 0; k < 8; ++k) sp[warp][lane * 8 + k] = sacc[k];
    __syncthreads();
    if (t < 256) {
        float sv = sBias[t];
#pragma unroll
        for (int w = 0; w < RWARPS; ++w) sv += sp[w][t];
        out[b * 256 + t] = squash_val(sv);
    }
}

extern "C" void kernel_launch(void* const* d_in, const int* in_sizes, int n_in,
                              void* d_out, int out_size) {
    const float* x    = (const float*)d_in[0];   // [128,1152,8]
    const float* W    = (const float*)d_in[1];   // [16,1152,16,8]
    const float* Bias = (const float*)d_in[2];   // [16,16]
    float* out = (float*)d_out;                  // [128,16,16]

    dim3 g1(ICHUNKS, NB / BC);   // (36, 16) = 576 CTAs
    k_hat<<<g1, 256>>>(x, W);
    k_route<<<NB, RWARPS * 32>>>(Bias, out);
}

// round 3
// speedup vs baseline: 2.2369x; 1.1272x over previous
#include <cuda_runtime.h>
#include <cuda_fp16.h>
#include <stdint.h>
#include <math.h>

#define NB 128
#define NI 1152
#define NN 16
#define NE 16
#define IC 32                  // i per k_hat CTA
#define ICHUNKS (NI/IC)        // 36
#define BC 16                  // b per k_hat CTA
#define BBLK (NB/BC)           // 8
#define SPLIT 4                // i-splits in routing passes
#define IPS (NI/SPLIT)         // 288
#define PSTEPS (IPS/16)        // 18 steps (16 i per block-step)

// Scratch (static device globals; no runtime allocation)
__device__ __half g_hat[(size_t)NB * NI * 256];   // [b][i][n*16+e], 75.5 MB
__device__ float  g_s0p[ICHUNKS * NB * 256];      // iter-0 partials per i-chunk
__device__ float  g_sp[SPLIT * NB * 256];         // per-split s partials
__device__ float  g_vec[NB * 256];                // cumulative sum of outputs

// ---- packed f32x2 helpers (Blackwell FFMA2 path, PTX-only) ----
__device__ __forceinline__ uint64_t pk(float a, float b) {
    uint64_t r; asm("mov.b64 %0, {%1,%2};" : "=l"(r) : "f"(a), "f"(b)); return r;
}
__device__ __forceinline__ void unpk(uint64_t v, float& lo, float& hi) {
    asm("mov.b64 {%0,%1}, %2;" : "=f"(lo), "=f"(hi) : "l"(v));
}
__device__ __forceinline__ uint64_t mul2(uint64_t a, uint64_t b) {
    uint64_t r; asm("mul.rn.f32x2 %0, %1, %2;" : "=l"(r) : "l"(a), "l"(b)); return r;
}
__device__ __forceinline__ void fma2(uint64_t& d, uint64_t a, uint64_t b) {
    asm("fma.rn.f32x2 %0, %1, %2, %3;" : "=l"(d) : "l"(a), "l"(b), "l"(d));
}
__device__ __forceinline__ void add2(uint64_t& d, uint64_t a) {
    asm("add.rn.f32x2 %0, %1, %2;" : "=l"(d) : "l"(a), "l"(d));
}

// ---------------------------------------------------------------------------
// k_hat: hat[b,i,n,e] = sum_d x[b,i,d] * W[n,i,e,d], fp16 out.
// grid (36 i-chunks, 8 b-blocks of 16). 256 threads: t = n*16 + e.
// Batches processed in pairs via packed f32x2 FMA: x pre-packed (x_b, x_b+1)
// in smem, W splat (w,w) hoisted per i. Also accumulates iter-0 partials.
// ---------------------------------------------------------------------------
__global__ void __launch_bounds__(256) k_hat(const float* __restrict__ x,
                                             const float* __restrict__ W) {
    __shared__ uint64_t sxp[8][IC][8];   // [b-pair][i][d] = (x_b, x_b+1), 16KB
    const int t  = threadIdx.x;
    const int i0 = blockIdx.x * IC;
    const int b0 = blockIdx.y * BC;

    for (int idx = t; idx < 8 * IC * 8; idx += 256) {
        int b2 = idx >> 8, rem = idx & 255;
        int ii = rem >> 3, d = rem & 7;
        float va = x[((size_t)(b0 + 2*b2    ) * NI + i0 + ii) * 8 + d];
        float vb = x[((size_t)(b0 + 2*b2 + 1) * NI + i0 + ii) * 8 + d];
        sxp[b2][ii][d] = pk(va, vb);
    }
    __syncthreads();

    const int n = t >> 4, e = t & 15;
    const float4* wp = reinterpret_cast<const float4*>(W)
                     + ((size_t)(n * NI + i0) * NE + e) * 2;

    uint64_t s0[8];
#pragma unroll
    for (int k = 0; k < 8; ++k) s0[k] = 0ull;   // (+0.0f, +0.0f)

    float4 wa = wp[0], wb = wp[1];
    for (int i = 0; i < IC; ++i) {
        float4 na, nb;
        if (i + 1 < IC) { na = wp[NE * 2]; nb = wp[NE * 2 + 1]; }
        wp += NE * 2;

        uint64_t ws[8];
        ws[0] = pk(wa.x, wa.x); ws[1] = pk(wa.y, wa.y);
        ws[2] = pk(wa.z, wa.z); ws[3] = pk(wa.w, wa.w);
        ws[4] = pk(wb.x, wb.x); ws[5] = pk(wb.y, wb.y);
        ws[6] = pk(wb.z, wb.z); ws[7] = pk(wb.w, wb.w);

#pragma unroll
        for (int b2 = 0; b2 < 8; ++b2) {
            const uint64_t* xp = &sxp[b2][i][0];
            uint64_t acc = mul2(ws[0], xp[0]);
            fma2(acc, ws[1], xp[1]);
            fma2(acc, ws[2], xp[2]);
            fma2(acc, ws[3], xp[3]);
            fma2(acc, ws[4], xp[4]);
            fma2(acc, ws[5], xp[5]);
            fma2(acc, ws[6], xp[6]);
            fma2(acc, ws[7], xp[7]);
            add2(s0[b2], acc);
            float lo, hi; unpk(acc, lo, hi);
            size_t base = ((size_t)(b0 + 2*b2) * NI + i0 + i) * 256 + t;
            g_hat[base]                    = __float2half_rn(lo);
            g_hat[base + (size_t)NI * 256] = __float2half_rn(hi);
        }
        wa = na; wb = nb;
    }
#pragma unroll
    for (int b2 = 0; b2 < 8; ++b2) {
        float lo, hi; unpk(s0[b2], lo, hi);
        g_s0p[((size_t)blockIdx.x * NB + b0 + 2*b2    ) * 256 + t] = lo;
        g_s0p[((size_t)blockIdx.x * NB + b0 + 2*b2 + 1) * 256 + t] = hi;
    }
}

// squash along e via warp butterfly over low 4 lane bits (t = n*16+e)
__device__ __forceinline__ float squash_val(float sv) {
    float sq = sv * sv;
    sq += __shfl_xor_sync(0xffffffffu, sq, 1);
    sq += __shfl_xor_sync(0xffffffffu, sq, 2);
    sq += __shfl_xor_sync(0xffffffffu, sq, 4);
    sq += __shfl_xor_sync(0xffffffffu, sq, 8);
    float scale = sq / ((1.f + sq) * sqrtf(sq));
    return sv * scale;
}

// ---------------------------------------------------------------------------
// k_pass: one routing sweep over hat for (b, i-split). Thread-per-(i,n):
// lane l -> n = l&15, islot = l>>4 (2 i per warp-step). Dot over e is
// in-register (no shfl); softmax denom over n = 4 shuffles. grid (128, 4).
// ---------------------------------------------------------------------------
__global__ void __launch_bounds__(256, 3) k_pass() {
    __shared__ float sVec[256];
    __shared__ float sRed[16][256];   // one slot per (warp,islot)

    const int b = blockIdx.x, isp = blockIdx.y;
    const int t = threadIdx.x, warp = t >> 5, lane = t & 31;
    const int n = lane & 15, islot = lane >> 4;

    sVec[t] = g_vec[b * 256 + t];
    __syncthreads();
    float vec[16];
#pragma unroll
    for (int k = 0; k < 16; ++k) vec[k] = sVec[n * 16 + k];

    const int iStart = isp * IPS + warp * 2 + islot;
    const uint4* p = reinterpret_cast<const uint4*>(g_hat)
                   + ((size_t)b * NI + iStart) * 32 + n * 2;
    const int STRIDE = 16 * 32;   // 16 i per block-step

    float sacc[16];
#pragma unroll
    for (int k = 0; k < 16; ++k) sacc[k] = 0.f;

    uint4 A0 = p[0], A1 = p[1];
    for (int s = 0; s < PSTEPS; ++s) {
        uint4 B0, B1;
        if (s + 1 < PSTEPS) { B0 = p[STRIDE]; B1 = p[STRIDE + 1]; }
        p += STRIDE;

        float f[16];
        const __half2* ha = reinterpret_cast<const __half2*>(&A0);
#pragma unroll
        for (int j = 0; j < 4; ++j) {
            float2 v = __half22float2(ha[j]); f[2*j] = v.x; f[2*j+1] = v.y;
        }
        const __half2* hb = reinterpret_cast<const __half2*>(&A1);
#pragma unroll
        for (int j = 0; j < 4; ++j) {
            float2 v = __half22float2(hb[j]); f[8+2*j] = v.x; f[8+2*j+1] = v.y;
        }

        // tree-reduced dot (4 independent chains)
        float d0 = vec[0]*f[0], d1 = vec[1]*f[1], d2 = vec[2]*f[2], d3 = vec[3]*f[3];
#pragma unroll
        for (int k = 4; k < 16; k += 4) {
            d0 = fmaf(vec[k],   f[k],   d0);
            d1 = fmaf(vec[k+1], f[k+1], d1);
            d2 = fmaf(vec[k+2], f[k+2], d2);
            d3 = fmaf(vec[k+3], f[k+3], d3);
        }
        float dot = (d0 + d1) + (d2 + d3);

        float E = __expf(dot);
        float den = E;
        den += __shfl_xor_sync(0xffffffffu, den, 1);
        den += __shfl_xor_sync(0xffffffffu, den, 2);
        den += __shfl_xor_sync(0xffffffffu, den, 4);
        den += __shfl_xor_sync(0xffffffffu, den, 8);
        float c = __fdividef(E, den);

#pragma unroll
        for (int k = 0; k < 16; ++k) sacc[k] = fmaf(c, f[k], sacc[k]);
        A0 = B0; A1 = B1;
    }

    const int slot = warp * 2 + islot;
#pragma unroll
    for (int k = 0; k < 16; ++k) sRed[slot][n * 16 + k] = sacc[k];
    __syncthreads();

    float sv = 0.f;
#pragma unroll
    for (int w = 0; w < 16; ++w) sv += sRed[w][t];
    g_sp[((size_t)isp * NB + b) * 256 + t] = sv;
}

// ---------------------------------------------------------------------------
// k_combine: reduce partials + bias, squash; update g_vec / write output.
// mode 0: iter-0 (from g_s0p, uniform softmax scale 1/16), g_vec = out
// mode 1: g_vec += out     mode 2: final, write d_out
// ---------------------------------------------------------------------------
__global__ void __launch_bounds__(256) k_combine(const float* __restrict__ Bias,
                                                 float* __restrict__ out, int mode) {
    const int b = blockIdx.x, t = threadIdx.x;
    float sv = 0.f;
    if (mode == 0) {
        for (int c = 0; c < ICHUNKS; ++c) sv += g_s0p[((size_t)c * NB + b) * 256 + t];
        sv *= (1.f / 16.f);
    } else {
#pragma unroll
        for (int c = 0; c < SPLIT; ++c) sv += g_sp[((size_t)c * NB + b) * 256 + t];
    }
    sv += Bias[t];
    float o = squash_val(sv);
    if (mode == 2)      out[b * 256 + t] = o;
    else if (mode == 0) g_vec[b * 256 + t] = o;
    else                g_vec[b * 256 + t] += o;
}

extern "C" void kernel_launch(void* const* d_in, const int* in_sizes, int n_in,
                              void* d_out, int out_size) {
    const float* x    = (const float*)d_in[0];   // [128,1152,8]
    const float* W    = (const float*)d_in[1];   // [16,1152,16,8]
    const float* Bias = (const float*)d_in[2];   // [16,16]
    float* out = (float*)d_out;                  // [128,16,16]

    k_hat<<<dim3(ICHUNKS, BBLK), 256>>>(x, W);
    k_combine<<<NB, 256>>>(Bias, out, 0);        // iter-0 squash -> g_vec
    k_pass<<<dim3(NB, SPLIT), 256>>>();          // pass 1 (b1 = out0 . hat)
    k_combine<<<NB, 256>>>(Bias, out, 1);        // out1; g_vec = out0+out1
    k_pass<<<dim3(NB, SPLIT), 256>>>();          // pass 2 (b2 = (out0+out1) . hat)
    k_combine<<<NB, 256>>>(Bias, out, 2);        // final squash -> d_out
}

// round 4
// speedup vs baseline: 2.6062x; 1.1651x over previous
#include <cuda_runtime.h>
#include <cuda_fp16.h>
#include <stdint.h>
#include <math.h>

#define NB 128
#define NI 1152
#define IC 16                  // i per k_hat CTA
#define ICHUNKS (NI/IC)        // 72
#define BC 16                  // b per k_hat CTA
#define BBLK (NB/BC)           // 8
#define SPLIT 4                // i-splits in routing passes
#define IPS (NI/SPLIT)         // 288
#define PSTEPS (IPS/16)        // 18 (16 i per CTA-step)

// Scratch (static device globals; no runtime allocation)
__device__ __half g_hat[(size_t)NB * NI * 256];   // [b][i][n*16+e], 75.5 MB
__device__ float  g_s0p[ICHUNKS * NB * 256];      // iter-0 partials per i-chunk
__device__ float  g_sp1[SPLIT * NB * 256];        // pass-1 s partials
__device__ float  g_sp2[SPLIT * NB * 256];        // pass-2 s partials
__device__ float  g_vec0[NB * 256];               // out0 (iter-0 output)

// ---- packed f32x2 helpers (Blackwell FFMA2 path, PTX-only) ----
__device__ __forceinline__ uint64_t pk(float a, float b) {
    uint64_t r; asm("mov.b64 %0, {%1,%2};" : "=l"(r) : "f"(a), "f"(b)); return r;
}
__device__ __forceinline__ void unpk(uint64_t v, float& lo, float& hi) {
    asm("mov.b64 {%0,%1}, %2;" : "=f"(lo), "=f"(hi) : "l"(v));
}
__device__ __forceinline__ uint64_t mul2(uint64_t a, uint64_t b) {
    uint64_t r; asm("mul.rn.f32x2 %0, %1, %2;" : "=l"(r) : "l"(a), "l"(b)); return r;
}
__device__ __forceinline__ void fma2(uint64_t& d, uint64_t a, uint64_t b) {
    asm("fma.rn.f32x2 %0, %1, %2, %3;" : "=l"(d) : "l"(a), "l"(b), "l"(d));
}
__device__ __forceinline__ void add2(uint64_t& d, uint64_t a) {
    asm("add.rn.f32x2 %0, %1, %2;" : "=l"(d) : "l"(a), "l"(d));
}

// ---------------------------------------------------------------------------
// k_hat: hat[b,i,n,e] = sum_d x[b,i,d] * W[n,i,e,d], fp16 out.
// grid (72 i-chunks of 16, 8 b-blocks of 16), 256 threads: t = n*16 + e.
// Batch pairs via packed f32x2 FMA. Also emits iter-0 partials (sum_i hat).
// ---------------------------------------------------------------------------
__global__ void __launch_bounds__(256) k_hat(const float* __restrict__ x,
                                             const float* __restrict__ W) {
    __shared__ uint64_t sxp[8][IC][8];   // [b-pair][i][d] = (x_b, x_b+1), 8KB
    const int t  = threadIdx.x;
    const int i0 = blockIdx.x * IC;
    const int b0 = blockIdx.y * BC;

    for (int idx = t; idx < 8 * IC * 8; idx += 256) {
        int b2 = idx >> 7, rem = idx & 127;
        int ii = rem >> 3, d = rem & 7;
        float va = x[((size_t)(b0 + 2*b2    ) * NI + i0 + ii) * 8 + d];
        float vb = x[((size_t)(b0 + 2*b2 + 1) * NI + i0 + ii) * 8 + d];
        sxp[b2][ii][d] = pk(va, vb);
    }
    __syncthreads();

    const float4* wp = reinterpret_cast<const float4*>(W)
                     + ((size_t)((t >> 4) * NI + i0) * 16 + (t & 15)) * 2;

    uint64_t s0[8];
#pragma unroll
    for (int k = 0; k < 8; ++k) s0[k] = 0ull;

    float4 wa = wp[0], wb = wp[1];
    for (int i = 0; i < IC; ++i) {
        float4 na, nb;
        if (i + 1 < IC) { na = wp[32]; nb = wp[33]; }
        wp += 32;

        uint64_t ws[8];
        ws[0] = pk(wa.x, wa.x); ws[1] = pk(wa.y, wa.y);
        ws[2] = pk(wa.z, wa.z); ws[3] = pk(wa.w, wa.w);
        ws[4] = pk(wb.x, wb.x); ws[5] = pk(wb.y, wb.y);
        ws[6] = pk(wb.z, wb.z); ws[7] = pk(wb.w, wb.w);

#pragma unroll
        for (int b2 = 0; b2 < 8; ++b2) {
            const uint64_t* xp = &sxp[b2][i][0];
            uint64_t acc = mul2(ws[0], xp[0]);
            fma2(acc, ws[1], xp[1]);
            fma2(acc, ws[2], xp[2]);
            fma2(acc, ws[3], xp[3]);
            fma2(acc, ws[4], xp[4]);
            fma2(acc, ws[5], xp[5]);
            fma2(acc, ws[6], xp[6]);
            fma2(acc, ws[7], xp[7]);
            add2(s0[b2], acc);
            float lo, hi; unpk(acc, lo, hi);
            size_t base = ((size_t)(b0 + 2*b2) * NI + i0 + i) * 256 + t;
            g_hat[base]                    = __float2half_rn(lo);
            g_hat[base + (size_t)NI * 256] = __float2half_rn(hi);
        }
        wa = na; wb = nb;
    }
#pragma unroll
    for (int b2 = 0; b2 < 8; ++b2) {
        float lo, hi; unpk(s0[b2], lo, hi);
        g_s0p[((size_t)blockIdx.x * NB + b0 + 2*b2    ) * 256 + t] = lo;
        g_s0p[((size_t)blockIdx.x * NB + b0 + 2*b2 + 1) * 256 + t] = hi;
    }
}

// squash along e via warp butterfly over low 4 lane bits (t = n*16+e)
__device__ __forceinline__ float squash_val(float sv) {
    float sq = sv * sv;
    sq += __shfl_xor_sync(0xffffffffu, sq, 1);
    sq += __shfl_xor_sync(0xffffffffu, sq, 2);
    sq += __shfl_xor_sync(0xffffffffu, sq, 4);
    sq += __shfl_xor_sync(0xffffffffu, sq, 8);
    float scale = sq / ((1.f + sq) * sqrtf(sq));
    return sv * scale;
}

// ---------------------------------------------------------------------------
// Process one i: fp16 hat fragment (16 e for this thread's n) -> logit dot,
// softmax coeff over n (4 shuffles), packed-fma accumulate into sacc.
// ---------------------------------------------------------------------------
__device__ __forceinline__ void step_i(uint4 A0, uint4 A1,
                                       const uint64_t vecp[8], uint64_t sacc[8]) {
    uint64_t fp[8];
    const __half2* ha = reinterpret_cast<const __half2*>(&A0);
#pragma unroll
    for (int j = 0; j < 4; ++j) {
        float2 v = __half22float2(ha[j]); fp[j] = pk(v.x, v.y);
    }
    const __half2* hb = reinterpret_cast<const __half2*>(&A1);
#pragma unroll
    for (int j = 0; j < 4; ++j) {
        float2 v = __half22float2(hb[j]); fp[4 + j] = pk(v.x, v.y);
    }

    uint64_t dacc = mul2(vecp[0], fp[0]);
#pragma unroll
    for (int j = 1; j < 8; ++j) fma2(dacc, vecp[j], fp[j]);
    float dlo, dhi; unpk(dacc, dlo, dhi);
    float dot = dlo + dhi;

    float E = __expf(dot);
    float den = E;
    den += __shfl_xor_sync(0xffffffffu, den, 1);
    den += __shfl_xor_sync(0xffffffffu, den, 2);
    den += __shfl_xor_sync(0xffffffffu, den, 4);
    den += __shfl_xor_sync(0xffffffffu, den, 8);
    float c = __fdividef(E, den);

    uint64_t cp = pk(c, c);
#pragma unroll
    for (int j = 0; j < 8; ++j) fma2(sacc[j], cp, fp[j]);
}

// ---------------------------------------------------------------------------
// k_pass: fused head (build vec from partials) + one routing sweep.
// stage 1: vec = out0 = squash(sum_i hat /16 + Bias)  [from g_s0p]
// stage 2: vec = out0 + out1                          [g_vec0, g_sp1]
// Thread-per-(i,n): lane l -> n = l&15, islot = l>>4. grid (128, SPLIT).
// ---------------------------------------------------------------------------
__global__ void __launch_bounds__(256) k_pass(const float* __restrict__ Bias,
                                              int stage) {
    __shared__ float sVec[256];
    __shared__ float sRed[16][256];

    const int b = blockIdx.x, isp = blockIdx.y;
    const int t = threadIdx.x, warp = t >> 5, lane = t & 31;
    const int n = lane & 15, islot = lane >> 4;

    // --- head: build vec for this batch (redundant per CTA, cheap) ---
    {
        float sv = 0.f;
        if (stage == 1) {
            for (int c = 0; c < ICHUNKS; ++c)
                sv += g_s0p[((size_t)c * NB + b) * 256 + t];
            sv = sv * (1.f / 16.f) + Bias[t];
            float o = squash_val(sv);
            sVec[t] = o;
            if (isp == 0) g_vec0[b * 256 + t] = o;
        } else {
#pragma unroll
            for (int c = 0; c < SPLIT; ++c)
                sv += g_sp1[((size_t)c * NB + b) * 256 + t];
            sv += Bias[t];
            sVec[t] = g_vec0[b * 256 + t] + squash_val(sv);
        }
    }
    __syncthreads();

    uint64_t vecp[8];
#pragma unroll
    for (int j = 0; j < 8; ++j)
        vecp[j] = pk(sVec[n * 16 + 2*j], sVec[n * 16 + 2*j + 1]);

    const int iStart = isp * IPS + warp * 2 + islot;
    const uint4* p = reinterpret_cast<const uint4*>(g_hat)
                   + ((size_t)b * NI + iStart) * 32 + n * 2;
    const int S = 16 * 32;   // 16 i per CTA-step, 32 uint4 per i

    uint64_t sacc[8];
#pragma unroll
    for (int j = 0; j < 8; ++j) sacc[j] = 0ull;

    // 2-step unroll, 4 LDG.128 in flight per lane
    uint4 A0 = p[0], A1 = p[1], B0 = p[S], B1 = p[S + 1];
    for (int s = 0; s < PSTEPS; s += 2) {
        uint4 C0, C1, D0, D1;
        if (s + 2 < PSTEPS) {
            C0 = p[2 * S]; C1 = p[2 * S + 1];
            D0 = p[3 * S]; D1 = p[3 * S + 1];
        }
        p += 2 * S;
        step_i(A0, A1, vecp, sacc);
        step_i(B0, B1, vecp, sacc);
        A0 = C0; A1 = C1; B0 = D0; B1 = D1;
    }

    const int slot = warp * 2 + islot;
#pragma unroll
    for (int j = 0; j < 8; ++j) {
        float lo, hi; unpk(sacc[j], lo, hi);
        sRed[slot][n * 16 + 2*j]     = lo;
        sRed[slot][n * 16 + 2*j + 1] = hi;
    }
    __syncthreads();

    float sv = 0.f;
#pragma unroll
    for (int w = 0; w < 16; ++w) sv += sRed[w][t];
    float* dst = (stage == 1) ? g_sp1 : g_sp2;
    dst[((size_t)isp * NB + b) * 256 + t] = sv;
}

// ---------------------------------------------------------------------------
// k_final: out = squash(sum_split g_sp2 + Bias). grid 128, 256 threads.
// ---------------------------------------------------------------------------
__global__ void __launch_bounds__(256) k_final(const float* __restrict__ Bias,
                                               float* __restrict__ out) {
    const int b = blockIdx.x, t = threadIdx.x;
    float sv = 0.f;
#pragma unroll
    for (int c = 0; c < SPLIT; ++c)
        sv += g_sp2[((size_t)c * NB + b) * 256 + t];
    sv += Bias[t];
    out[b * 256 + t] = squash_val(sv);
}

extern "C" void kernel_launch(void* const* d_in, const int* in_sizes, int n_in,
                              void* d_out, int out_size) {
    const float* x    = (const float*)d_in[0];   // [128,1152,8]
    const float* W    = (const float*)d_in[1];   // [16,1152,16,8]
    const float* Bias = (const float*)d_in[2];   // [16,16]
    float* out = (float*)d_out;                  // [128,16,16]

    k_hat<<<dim3(ICHUNKS, BBLK), 256>>>(x, W);   // 576 CTAs
    k_pass<<<dim3(NB, SPLIT), 256>>>(Bias, 1);   // pass 1 (head: iter-0 squash)
    k_pass<<<dim3(NB, SPLIT), 256>>>(Bias, 2);   // pass 2 (head: out1, telescope)
    k_final<<<NB, 256>>>(Bias, out);
}